// round 15
// baseline (speedup 1.0000x reference)
#include <cuda_runtime.h>
#include <cuda_bf16.h>
#include <cstdint>

#define BB   4
#define SS   2048
#define DD   1024
#define HH   16
#define DHH  64
#define MTOK (BB * SS)          // 8192
#define NQKV (3 * HH * DHH)     // 3072

typedef __nv_bfloat16  bf16;
typedef __nv_bfloat162 bf162;

// ---------------------------------------------------------------------------
// Scratch (static __device__ arrays; no allocation allowed)
// ---------------------------------------------------------------------------
__device__ bf16  g_inpb [(size_t)MTOK * DD];     // 16 MB
__device__ bf16  g_wqkvb[(size_t)NQKV * DD];     // 6 MB
__device__ bf16  g_wob  [(size_t)DD * DD];       // 2 MB
__device__ bf16  g_qb   [(size_t)MTOK * DD];     // 16 MB  Q projections
__device__ bf16  g_kc   [(size_t)MTOK * DD];     // 16 MB  compact K
__device__ bf16  g_vc   [(size_t)MTOK * DD];     // 16 MB  compact V
__device__ bf16  g_attnb[(size_t)MTOK * DD];     // 16 MB
__device__ float g_y    [(size_t)MTOK * DD];     // 32 MB
__device__ int   g_idx  [BB * SS];
__device__ int   g_cnt  [BB];

// ---------------------------------------------------------------------------
// Helpers: ldmatrix / mma.sync (sm_80 PTX) + cp.async + griddepcontrol
// ---------------------------------------------------------------------------
__device__ __forceinline__ uint32_t su32(const void* p) {
    return (uint32_t)__cvta_generic_to_shared(p);
}
__device__ __forceinline__ void ldm4(uint32_t& r0, uint32_t& r1, uint32_t& r2,
                                     uint32_t& r3, uint32_t a) {
    asm volatile("ldmatrix.sync.aligned.m8n8.x4.shared.b16 {%0,%1,%2,%3},[%4];\n"
                 : "=r"(r0), "=r"(r1), "=r"(r2), "=r"(r3) : "r"(a));
}
__device__ __forceinline__ void ldm4t(uint32_t& r0, uint32_t& r1, uint32_t& r2,
                                      uint32_t& r3, uint32_t a) {
    asm volatile("ldmatrix.sync.aligned.m8n8.x4.trans.shared.b16 {%0,%1,%2,%3},[%4];\n"
                 : "=r"(r0), "=r"(r1), "=r"(r2), "=r"(r3) : "r"(a));
}
__device__ __forceinline__ void mmabf(float* c, const uint32_t* a,
                                      uint32_t b0, uint32_t b1) {
    asm volatile(
        "mma.sync.aligned.m16n8k16.row.col.f32.bf16.bf16.f32 "
        "{%0,%1,%2,%3},{%4,%5,%6,%7},{%8,%9},{%0,%1,%2,%3};\n"
        : "+f"(c[0]), "+f"(c[1]), "+f"(c[2]), "+f"(c[3])
        : "r"(a[0]), "r"(a[1]), "r"(a[2]), "r"(a[3]), "r"(b0), "r"(b1));
}
__device__ __forceinline__ uint32_t packbf(float x, float y) {
    bf162 t = __floats2bfloat162_rn(x, y);
    return *reinterpret_cast<uint32_t*>(&t);
}
__device__ __forceinline__ void cpa16(uint32_t dst, const void* src) {
    asm volatile("cp.async.cg.shared.global [%0], [%1], 16;\n" :: "r"(dst), "l"(src));
}
#define CPCOMMIT() asm volatile("cp.async.commit_group;\n" ::: "memory")
#define CPWAIT(n)  asm volatile("cp.async.wait_group %0;\n" :: "n"(n) : "memory")
#define GDWAIT()   asm volatile("griddepcontrol.wait;" ::: "memory")
#define GDTRIG()   asm volatile("griddepcontrol.launch_dependents;" ::: "memory")

// ---------------------------------------------------------------------------
// Fused preprocessing: 3x f2bf + key compaction, one launch.
// ---------------------------------------------------------------------------
#define PRE_INP  (MTOK * DD / 1024)            // 8192
#define PRE_WQKV (NQKV * DD / 1024)            // 3072
#define PRE_WO   (DD * DD / 1024)              // 1024
#define PRE_TOTAL (PRE_INP + PRE_WQKV + PRE_WO + BB)

__global__ __launch_bounds__(256)
void preproc(const float* __restrict__ inp, const float* __restrict__ Wqkv,
             const float* __restrict__ Wo, const int* __restrict__ mask,
             bf16* __restrict__ inpb, bf16* __restrict__ wqkvb,
             bf16* __restrict__ wob, int* __restrict__ idx, int* __restrict__ cnt)
{
    const int bid = blockIdx.x, tid = threadIdx.x;
    if (bid < PRE_INP + PRE_WQKV + PRE_WO) {
        const float* src; bf16* dst; int blk;
        if (bid < PRE_INP)                 { src = inp;  dst = inpb;  blk = bid; }
        else if (bid < PRE_INP + PRE_WQKV) { src = Wqkv; dst = wqkvb; blk = bid - PRE_INP; }
        else                               { src = Wo;   dst = wob;   blk = bid - PRE_INP - PRE_WQKV; }
        int i = blk * 1024 + tid * 4;
        float4 v = *(const float4*)(src + i);
        bf162* o = (bf162*)(dst + i);
        o[0] = __floats2bfloat162_rn(v.x, v.y);
        o[1] = __floats2bfloat162_rn(v.z, v.w);
        GDTRIG();
        return;
    }
    // --- key compaction for batch b ---
    const int b = bid - (PRE_INP + PRE_WQKV + PRE_WO);
    const int lane = tid & 31, wid = tid >> 5;
    const int* mrow = mask + b * SS;
    __shared__ int ws[8];

    int lm[8], local = 0;
#pragma unroll
    for (int i = 0; i < 8; i++) { lm[i] = (mrow[tid * 8 + i] == 0); local += lm[i]; }

    int inc = local;
#pragma unroll
    for (int off = 1; off < 32; off <<= 1) {
        int n = __shfl_up_sync(0xffffffffu, inc, off);
        if (lane >= off) inc += n;
    }
    if (lane == 31) ws[wid] = inc;
    __syncthreads();
    if (tid == 0) {
        int run = 0;
#pragma unroll
        for (int w = 0; w < 8; w++) { int t = ws[w]; ws[w] = run; run += t; }
        cnt[b] = run;
    }
    __syncthreads();

    int pos = ws[wid] + inc - local;
#pragma unroll
    for (int i = 0; i < 8; i++)
        if (lm[i]) { idx[b * SS + pos] = tid * 8 + i; pos++; }
    GDTRIG();
}

// ---------------------------------------------------------------------------
// Big-tile GEMM constants (qkv): CTA 128x256, warp tile 64x64, K-chunk 64,
// 3-stage cp.async ring in dynamic smem.
// ---------------------------------------------------------------------------
#define GLD    72
#define A_SZ   (128 * GLD)
#define B_SZ   (256 * GLD)
#define STAGE_ELEMS (A_SZ + B_SZ)
#define GSMEM_BYTES (3 * STAGE_ELEMS * 2)   // 165888

// ---------------------------------------------------------------------------
// Unified QKV GEMM (blocks [0,256): Q ; [256,768): gathered KV).
// ---------------------------------------------------------------------------
__global__ __launch_bounds__(256, 1)
void qkv_gemm(const bf16* __restrict__ inpb, const bf16* __restrict__ wqkvb,
              const float* __restrict__ bqkv, const int* __restrict__ idx,
              const int* __restrict__ cnt, bf16* __restrict__ qb,
              bf16* __restrict__ kc, bf16* __restrict__ vc)
{
    extern __shared__ __align__(16) bf16 smem[];
    __shared__ int sidx[128];

    GDWAIT();   // upstream (preproc) complete; inputs visible

    const int bid = blockIdx.x;
    const bool isQ = bid < 256;
    const int tid  = threadIdx.x;
    const int wid  = tid >> 5, lane = tid & 31;
    const int wm   = (wid >> 2) << 6;
    const int wn   = (wid & 3) << 6;
    const int r8 = tid >> 3, sg = tid & 7;

    int m0, n0, b = 0, c_ = 0;
    if (isQ) {
        n0 = (bid & 3) << 8;
        m0 = (bid >> 2) << 7;
    } else {
        const int t = bid - 256;
        b  = t >> 7;
        const int r = t & 127;
        n0 = (r & 7) << 8;
        m0 = (r >> 3) << 7;
        c_ = cnt[b];
        if (m0 >= ((c_ + 127) & ~127)) { GDTRIG(); return; }
    }

    if (tid < 128) {
        int j = m0 + tid;
        sidx[tid] = isQ ? j : ((j < c_) ? idx[b * SS + j] : 0);
    }
    __syncthreads();

    const bf16* A = inpb + (isQ ? 0 : (size_t)b * SS * DD);
    const bf16* W = wqkvb + (isQ ? 0 : (size_t)DD * DD);
    const float* bias = bqkv + (isQ ? 0 : DD);

    float acc[4][8][4];
#pragma unroll
    for (int i = 0; i < 4; i++)
#pragma unroll
        for (int j = 0; j < 8; j++)
#pragma unroll
            for (int e = 0; e < 4; e++) acc[i][j][e] = 0.0f;

    const int nk = DD >> 6;

    auto load_stage = [&](int kt) {
        bf16* As = smem + (kt % 3) * STAGE_ELEMS;
        bf16* Bs = As + A_SZ;
        const int kofs = kt << 6;
#pragma unroll
        for (int i = 0; i < 4; i++) {
            int r = r8 + i * 32;
            cpa16(su32(&As[r * GLD + sg * 8]),
                  &A[(size_t)sidx[r] * DD + kofs + sg * 8]);
        }
#pragma unroll
        for (int i = 0; i < 8; i++) {
            int r = r8 + i * 32;
            cpa16(su32(&Bs[r * GLD + sg * 8]),
                  &W[(size_t)(n0 + r) * DD + kofs + sg * 8]);
        }
        CPCOMMIT();
    };

    load_stage(0);
    load_stage(1);

    for (int kt = 0; kt < nk; kt++) {
        CPWAIT(1);
        __syncthreads();

        if (kt + 2 < nk) load_stage(kt + 2); else CPCOMMIT();

        const bf16* As = smem + (kt % 3) * STAGE_ELEMS;
        const bf16* Bs = As + A_SZ;

#pragma unroll
        for (int ks = 0; ks < 4; ks++) {
            uint32_t af[4][4], bfr[8][2];
#pragma unroll
            for (int mf = 0; mf < 4; mf++) {
                uint32_t ad = su32(&As[(wm + mf * 16 + (lane & 15)) * GLD +
                                       ks * 16 + (lane >> 4) * 8]);
                ldm4(af[mf][0], af[mf][1], af[mf][2], af[mf][3], ad);
            }
#pragma unroll
            for (int p = 0; p < 4; p++) {
                uint32_t bd = su32(&Bs[(wn + p * 16 + (lane & 7) + ((lane >> 4) << 3)) * GLD +
                                       ks * 16 + ((lane >> 3) & 1) * 8]);
                ldm4(bfr[2 * p][0], bfr[2 * p][1], bfr[2 * p + 1][0], bfr[2 * p + 1][1], bd);
            }
#pragma unroll
            for (int mf = 0; mf < 4; mf++)
#pragma unroll
                for (int nf = 0; nf < 8; nf++)
                    mmabf(acc[mf][nf], af[mf], bfr[nf][0], bfr[nf][1]);
        }
    }

    GDTRIG();   // dependents may get resident while we run the epilogue

    if (isQ) {
#pragma unroll
        for (int mf = 0; mf < 4; mf++) {
            const int r = m0 + wm + mf * 16 + (lane >> 2);
#pragma unroll
            for (int nf = 0; nf < 8; nf++) {
                const int c = n0 + wn + nf * 8 + (lane & 3) * 2;
                float b0v = bias[c], b1v = bias[c + 1];
                *(bf162*)&qb[(size_t)r * DD + c] =
                    __floats2bfloat162_rn(acc[mf][nf][0] + b0v, acc[mf][nf][1] + b1v);
                *(bf162*)&qb[(size_t)(r + 8) * DD + c] =
                    __floats2bfloat162_rn(acc[mf][nf][2] + b0v, acc[mf][nf][3] + b1v);
            }
        }
    } else {
#pragma unroll
        for (int mf = 0; mf < 4; mf++) {
            const int j = m0 + wm + mf * 16 + (lane >> 2);
#pragma unroll
            for (int nf = 0; nf < 8; nf++) {
                const int c = n0 + wn + nf * 8 + (lane & 3) * 2;
                float b0v = bias[c], b1v = bias[c + 1];
                float v0 = acc[mf][nf][0] + b0v, v1 = acc[mf][nf][1] + b1v;
                float v2 = acc[mf][nf][2] + b0v, v3 = acc[mf][nf][3] + b1v;
                if (j >= c_)     { v0 = 0.0f; v1 = 0.0f; }
                if (j + 8 >= c_) { v2 = 0.0f; v3 = 0.0f; }
                bf16* dst = (c < DD) ? kc : vc;
                const int cc = (c < DD) ? c : c - DD;
                *(bf162*)&dst[(size_t)(b * SS + j) * DD + cc]     = __floats2bfloat162_rn(v0, v1);
                *(bf162*)&dst[(size_t)(b * SS + j + 8) * DD + cc] = __floats2bfloat162_rn(v2, v3);
            }
        }
    }
}

// ---------------------------------------------------------------------------
// Out-proj GEMM, R7-proven occupancy-2 config: CTA 128x128, 8 warps,
// warp tile 64x32, K-chunk 32, 2-stage cp.async ring, static smem (40 KB),
// ~96 regs -> 2 CTAs/SM. Grid 512 CTAs = 1.73 waves at double capacity.
// y = attn @ Wo^T + inp (fp32 out).
// ---------------------------------------------------------------------------
#define LDT 40
__global__ __launch_bounds__(256, 2)
void hgemm_proj(const bf16* __restrict__ A, const bf16* __restrict__ W,
                const float* __restrict__ res, float* __restrict__ C,
                int M, int N, int K)
{
    __shared__ __align__(16) bf16 As[2][128 * LDT];   // 2 x 10 KB
    __shared__ __align__(16) bf16 Bs[2][128 * LDT];   // 2 x 10 KB

    GDWAIT();

    const int tid  = threadIdx.x;
    const int wid  = tid >> 5, lane = tid & 31;
    const int m0   = blockIdx.y << 7, n0 = blockIdx.x << 7;
    const int wm   = (wid >> 2) << 6, wn = (wid & 3) << 5;
    const int r0c = tid >> 2, sg0 = tid & 3;

    float acc[4][4][4];
#pragma unroll
    for (int i = 0; i < 4; i++)
#pragma unroll
        for (int j = 0; j < 4; j++)
#pragma unroll
            for (int e = 0; e < 4; e++) acc[i][j][e] = 0.0f;

    const int nk = K >> 5;

    auto load_stage = [&](int kt, int buf) {
        const int kofs = kt * 32;
#pragma unroll
        for (int i = 0; i < 2; i++) {
            int r = r0c + i * 64;
            cpa16(su32(&As[buf][r * LDT + sg0 * 8]),
                  &A[(size_t)(m0 + r) * K + kofs + sg0 * 8]);
        }
#pragma unroll
        for (int i = 0; i < 2; i++) {
            int r = r0c + i * 64;
            cpa16(su32(&Bs[buf][r * LDT + sg0 * 8]),
                  &W[(size_t)(n0 + r) * K + kofs + sg0 * 8]);
        }
        CPCOMMIT();
    };

    load_stage(0, 0);

    for (int kt = 0; kt < nk; kt++) {
        const int buf = kt & 1;
        CPWAIT(0);
        __syncthreads();

        if (kt + 1 < nk) load_stage(kt + 1, buf ^ 1);

#pragma unroll
        for (int ks = 0; ks < 2; ks++) {
            uint32_t af[4][4], bfr[4][2];
#pragma unroll
            for (int mf = 0; mf < 4; mf++) {
                uint32_t ad = su32(&As[buf][(wm + mf * 16 + (lane & 15)) * LDT +
                                            ks * 16 + (lane >> 4) * 8]);
                ldm4(af[mf][0], af[mf][1], af[mf][2], af[mf][3], ad);
            }
#pragma unroll
            for (int p = 0; p < 2; p++) {
                uint32_t bd = su32(&Bs[buf][(wn + p * 16 + (lane & 7) + ((lane >> 4) << 3)) * LDT +
                                            ks * 16 + ((lane >> 3) & 1) * 8]);
                ldm4(bfr[2 * p][0], bfr[2 * p][1], bfr[2 * p + 1][0], bfr[2 * p + 1][1], bd);
            }
#pragma unroll
            for (int mf = 0; mf < 4; mf++)
#pragma unroll
                for (int nf = 0; nf < 4; nf++)
                    mmabf(acc[mf][nf], af[mf], bfr[nf][0], bfr[nf][1]);
        }
        __syncthreads();
    }

    GDTRIG();

#pragma unroll
    for (int mf = 0; mf < 4; mf++) {
        const int r = m0 + wm + mf * 16 + (lane >> 2);
#pragma unroll
        for (int nf = 0; nf < 4; nf++) {
            const int c = n0 + wn + nf * 8 + (lane & 3) * 2;
            float2 q0 = *(const float2*)&res[(size_t)r * N + c];
            float2 q1 = *(const float2*)&res[(size_t)(r + 8) * N + c];
            *(float2*)&C[(size_t)r * N + c] =
                make_float2(acc[mf][nf][0] + q0.x, acc[mf][nf][1] + q0.y);
            *(float2*)&C[(size_t)(r + 8) * N + c] =
                make_float2(acc[mf][nf][2] + q1.x, acc[mf][nf][3] + q1.y);
        }
    }
}

// ---------------------------------------------------------------------------
// bf16 flash attention over COMPACTED keys (3-stage cp.async K/V ring).
// ---------------------------------------------------------------------------
#define LQT 72
#define FQ_ELEMS  (128 * LQT)
#define FKV_STAGE (2 * 64 * LQT)
#define FSMEM_BYTES ((FQ_ELEMS + 3 * FKV_STAGE) * 2)   // 73728

__global__ __launch_bounds__(256)
void flash_bf16(const bf16* __restrict__ qp, const bf16* __restrict__ kc,
                const bf16* __restrict__ vc, const int* __restrict__ cnt,
                bf16* __restrict__ attn)
{
    extern __shared__ __align__(16) bf16 fsm[];
    bf16* Qs = fsm;

    GDWAIT();

    const int tid = threadIdx.x, wid = tid >> 5, lane = tid & 31;
    const int b = blockIdx.x >> 4, h = blockIdx.x & 15;
    const int q0 = blockIdx.y << 7;

    const int c_ = cnt[b];
    const int T = ((c_ + 63) & ~63) >> 6;

    const bf16* qb  = qp + (size_t)(b * SS + q0) * DD + h * DHH;
    const bf16* kcb = kc + (size_t)b * SS * DD + h * DHH;
    const bf16* vcb = vc + (size_t)b * SS * DD + h * DHH;

    auto load_kv = [&](int t) {
        bf16* Ks = fsm + FQ_ELEMS + (t % 3) * FKV_STAGE;
        bf16* Vs = Ks + 64 * LQT;
        const int kb0 = t << 6;
#pragma unroll
        for (int i = 0; i < 2; i++) {
            int e = i * 256 + tid, r = e >> 3, sgq = e & 7;
            cpa16(su32(&Ks[r * LQT + sgq * 8]), &kcb[(size_t)(kb0 + r) * DD + sgq * 8]);
            cpa16(su32(&Vs[r * LQT + sgq * 8]), &vcb[(size_t)(kb0 + r) * DD + sgq * 8]);
        }
        CPCOMMIT();
    };

    load_kv(0);
    if (T > 1) load_kv(1); else CPCOMMIT();

#pragma unroll
    for (int i = 0; i < 4; i++) {
        int e = i * 256 + tid, r = e >> 3, sgq = e & 7;
        *(uint4*)&Qs[r * LQT + sgq * 8] = *(const uint4*)&qb[(size_t)r * DD + sgq * 8];
    }
    __syncthreads();

    uint32_t qf[4][4];
#pragma unroll
    for (int ks = 0; ks < 4; ks++) {
        uint32_t ad = su32(&Qs[(wid * 16 + (lane & 15)) * LQT + ks * 16 + (lane >> 4) * 8]);
        ldm4(qf[ks][0], qf[ks][1], qf[ks][2], qf[ks][3], ad);
    }

    float m0v = -1e30f, m1v = -1e30f, l0 = 0.0f, l1 = 0.0f;
    float o[8][4];
#pragma unroll
    for (int nf = 0; nf < 8; nf++)
#pragma unroll
        for (int e = 0; e < 4; e++) o[nf][e] = 0.0f;

    for (int t = 0; t < T; t++) {
        CPWAIT(1);
        __syncthreads();
        if (t + 2 < T) load_kv(t + 2); else CPCOMMIT();

        const bf16* Ks = fsm + FQ_ELEMS + (t % 3) * FKV_STAGE;
        const bf16* Vs = Ks + 64 * LQT;
        const int kb0 = t << 6;

        float sv[8][4];
#pragma unroll
        for (int nf = 0; nf < 8; nf++)
#pragma unroll
            for (int e = 0; e < 4; e++) sv[nf][e] = 0.0f;

#pragma unroll
        for (int ks = 0; ks < 4; ks++) {
            uint32_t kf[8][2];
#pragma unroll
            for (int p = 0; p < 4; p++) {
                uint32_t bd = su32(&Ks[(p * 16 + (lane & 7) + ((lane >> 4) << 3)) * LQT +
                                       ks * 16 + ((lane >> 3) & 1) * 8]);
                ldm4(kf[2 * p][0], kf[2 * p][1], kf[2 * p + 1][0], kf[2 * p + 1][1], bd);
            }
#pragma unroll
            for (int nf = 0; nf < 8; nf++)
                mmabf(sv[nf], qf[ks], kf[nf][0], kf[nf][1]);
        }

        const int c2 = (lane & 3) * 2;
#pragma unroll
        for (int nf = 0; nf < 8; nf++) {
            int kidx = kb0 + nf * 8 + c2;
            bool v0 = kidx < c_, v1 = (kidx + 1) < c_;
            sv[nf][0] = v0 ? sv[nf][0] * 0.125f : -1e30f;
            sv[nf][1] = v1 ? sv[nf][1] * 0.125f : -1e30f;
            sv[nf][2] = v0 ? sv[nf][2] * 0.125f : -1e30f;
            sv[nf][3] = v1 ? sv[nf][3] * 0.125f : -1e30f;
        }

        float mx0 = -1e30f, mx1 = -1e30f;
#pragma unroll
        for (int nf = 0; nf < 8; nf++) {
            mx0 = fmaxf(mx0, fmaxf(sv[nf][0], sv[nf][1]));
            mx1 = fmaxf(mx1, fmaxf(sv[nf][2], sv[nf][3]));
        }
        mx0 = fmaxf(mx0, __shfl_xor_sync(0xffffffffu, mx0, 1));
        mx0 = fmaxf(mx0, __shfl_xor_sync(0xffffffffu, mx0, 2));
        mx1 = fmaxf(mx1, __shfl_xor_sync(0xffffffffu, mx1, 1));
        mx1 = fmaxf(mx1, __shfl_xor_sync(0xffffffffu, mx1, 2));

        float mn0 = fmaxf(m0v, mx0), mn1 = fmaxf(m1v, mx1);
        float al0 = __expf(m0v - mn0), al1 = __expf(m1v - mn1);
        m0v = mn0; m1v = mn1;

        float sum0 = 0.0f, sum1 = 0.0f;
#pragma unroll
        for (int nf = 0; nf < 8; nf++) {
            sv[nf][0] = __expf(sv[nf][0] - mn0);
            sv[nf][1] = __expf(sv[nf][1] - mn0);
            sv[nf][2] = __expf(sv[nf][2] - mn1);
            sv[nf][3] = __expf(sv[nf][3] - mn1);
            sum0 += sv[nf][0] + sv[nf][1];
            sum1 += sv[nf][2] + sv[nf][3];
        }
        sum0 += __shfl_xor_sync(0xffffffffu, sum0, 1);
        sum0 += __shfl_xor_sync(0xffffffffu, sum0, 2);
        sum1 += __shfl_xor_sync(0xffffffffu, sum1, 1);
        sum1 += __shfl_xor_sync(0xffffffffu, sum1, 2);
        l0 = l0 * al0 + sum0;
        l1 = l1 * al1 + sum1;
#pragma unroll
        for (int nf = 0; nf < 8; nf++) {
            o[nf][0] *= al0; o[nf][1] *= al0;
            o[nf][2] *= al1; o[nf][3] *= al1;
        }

#pragma unroll
        for (int ks = 0; ks < 4; ks++) {
            uint32_t pa[4];
            pa[0] = packbf(sv[2 * ks][0],     sv[2 * ks][1]);
            pa[1] = packbf(sv[2 * ks][2],     sv[2 * ks][3]);
            pa[2] = packbf(sv[2 * ks + 1][0], sv[2 * ks + 1][1]);
            pa[3] = packbf(sv[2 * ks + 1][2], sv[2 * ks + 1][3]);
#pragma unroll
            for (int p = 0; p < 4; p++) {
                uint32_t v0, v1, v2, v3;
                uint32_t vd = su32(&Vs[(ks * 16 + (lane & 7) + (((lane >> 3) & 1) << 3)) * LQT +
                                       p * 16 + ((lane >> 4) << 3)]);
                ldm4t(v0, v1, v2, v3, vd);
                mmabf(o[2 * p],     pa, v0, v1);
                mmabf(o[2 * p + 1], pa, v2, v3);
            }
        }
    }

    GDTRIG();

    const float i0 = 1.0f / l0, i1 = 1.0f / l1;
    const int r0 = q0 + wid * 16 + (lane >> 2);
    bf16* ob = attn + (size_t)b * SS * DD + h * DHH;
#pragma unroll
    for (int nf = 0; nf < 8; nf++) {
        int c = nf * 8 + (lane & 3) * 2;
        *(bf162*)&ob[(size_t)r0 * DD + c] =
            __floats2bfloat162_rn(o[nf][0] * i0, o[nf][1] * i0);
        *(bf162*)&ob[(size_t)(r0 + 8) * DD + c] =
            __floats2bfloat162_rn(o[nf][2] * i1, o[nf][3] * i1);
    }
}

// ---------------------------------------------------------------------------
// LayerNorm: one WARP per row (8 rows/block).
// ---------------------------------------------------------------------------
__global__ __launch_bounds__(256)
void ln_kernel(const float* __restrict__ y, const float* __restrict__ gamma,
               const float* __restrict__ beta, float* __restrict__ out)
{
    GDWAIT();

    const int wid = threadIdx.x >> 5, lane = threadIdx.x & 31;
    const int row = blockIdx.x * 8 + wid;
    const float* yr = y + (size_t)row * DD;

    float4 v[8];
    float s = 0.0f, s2 = 0.0f;
#pragma unroll
    for (int i = 0; i < 8; i++) {
        v[i] = *(const float4*)&yr[lane * 4 + i * 128];
        s  += v[i].x + v[i].y + v[i].z + v[i].w;
        s2 += v[i].x * v[i].x + v[i].y * v[i].y + v[i].z * v[i].z + v[i].w * v[i].w;
    }
#pragma unroll
    for (int off = 16; off; off >>= 1) {
        s  += __shfl_xor_sync(0xffffffffu, s,  off);
        s2 += __shfl_xor_sync(0xffffffffu, s2, off);
    }

    const float mean = s * (1.0f / DD);
    const float var  = s2 * (1.0f / DD) - mean * mean;
    const float inv  = rsqrtf(var + 1e-5f);

#pragma unroll
    for (int i = 0; i < 8; i++) {
        const int c = lane * 4 + i * 128;
        float4 g  = *(const float4*)&gamma[c];
        float4 bt = *(const float4*)&beta[c];
        float4 r;
        r.x = (v[i].x - mean) * inv * g.x + bt.x;
        r.y = (v[i].y - mean) * inv * g.y + bt.y;
        r.z = (v[i].z - mean) * inv * g.z + bt.z;
        r.w = (v[i].w - mean) * inv * g.w + bt.w;
        *(float4*)&out[(size_t)row * DD + c] = r;
    }
}

// ---------------------------------------------------------------------------
extern "C" void kernel_launch(void* const* d_in, const int* in_sizes, int n_in,
                              void* d_out, int out_size)
{
    (void)in_sizes; (void)n_in; (void)out_size;
    const float* inp   = (const float*)d_in[0];
    const int*   mask  = (const int*)d_in[1];
    const float* Wqkv  = (const float*)d_in[2];
    const float* bqkv  = (const float*)d_in[3];
    const float* Wo    = (const float*)d_in[4];
    const float* gamma = (const float*)d_in[5];
    const float* beta  = (const float*)d_in[6];
    float* out = (float*)d_out;

    bf16 *inpb, *wqkvb, *wob, *qb, *kc, *vc, *attnb;
    float* y;
    int *idx, *cnt;
    cudaGetSymbolAddress((void**)&inpb,  g_inpb);
    cudaGetSymbolAddress((void**)&wqkvb, g_wqkvb);
    cudaGetSymbolAddress((void**)&wob,   g_wob);
    cudaGetSymbolAddress((void**)&qb,    g_qb);
    cudaGetSymbolAddress((void**)&kc,    g_kc);
    cudaGetSymbolAddress((void**)&vc,    g_vc);
    cudaGetSymbolAddress((void**)&attnb, g_attnb);
    cudaGetSymbolAddress((void**)&y,     g_y);
    cudaGetSymbolAddress((void**)&idx,   g_idx);
    cudaGetSymbolAddress((void**)&cnt,   g_cnt);

    cudaFuncSetAttribute(qkv_gemm,
                         cudaFuncAttributeMaxDynamicSharedMemorySize, GSMEM_BYTES);
    cudaFuncSetAttribute(flash_bf16,
                         cudaFuncAttributeMaxDynamicSharedMemorySize, FSMEM_BYTES);

    // PDL launch attribute (dependent may start during predecessor's epilogue)
    cudaLaunchAttribute pdl[1];
    pdl[0].id = cudaLaunchAttributeProgrammaticStreamSerialization;
    pdl[0].val.programmaticStreamSerializationAllowed = 1;

    // 0) fused conversions + key compaction
    preproc<<<PRE_TOTAL, 256>>>(inp, Wqkv, Wo, mask, inpb, wqkvb, wob, idx, cnt);

    // 1) unified Q + gathered-KV GEMM
    {
        cudaLaunchConfig_t cfg = {};
        cfg.gridDim = dim3(768, 1, 1); cfg.blockDim = dim3(256, 1, 1);
        cfg.dynamicSmemBytes = GSMEM_BYTES; cfg.stream = 0;
        cfg.attrs = pdl; cfg.numAttrs = 1;
        cudaLaunchKernelEx(&cfg, qkv_gemm, inpb, wqkvb, bqkv,
                           (const int*)idx, (const int*)cnt, qb, kc, vc);
    }

    // 2) attention over ~cnt keys
    {
        cudaLaunchConfig_t cfg = {};
        cfg.gridDim = dim3(BB * HH, SS / 128, 1); cfg.blockDim = dim3(256, 1, 1);
        cfg.dynamicSmemBytes = FSMEM_BYTES; cfg.stream = 0;
        cfg.attrs = pdl; cfg.numAttrs = 1;
        cudaLaunchKernelEx(&cfg, flash_bf16, (const bf16*)qb, (const bf16*)kc,
                           (const bf16*)vc, (const int*)cnt, attnb);
    }

    // 3) y = inp + attn @ Wo^T  (occupancy-2 config, 512 CTAs)
    {
        cudaLaunchConfig_t cfg = {};
        cfg.gridDim = dim3(DD / 128, MTOK / 128, 1); cfg.blockDim = dim3(256, 1, 1);
        cfg.dynamicSmemBytes = 0; cfg.stream = 0;
        cfg.attrs = pdl; cfg.numAttrs = 1;
        cudaLaunchKernelEx(&cfg, hgemm_proj, (const bf16*)attnb, (const bf16*)wob,
                           inp, y, MTOK, DD, DD);
    }

    // 4) out = LayerNorm(y)
    {
        cudaLaunchConfig_t cfg = {};
        cfg.gridDim = dim3(MTOK / 8, 1, 1); cfg.blockDim = dim3(256, 1, 1);
        cfg.dynamicSmemBytes = 0; cfg.stream = 0;
        cfg.attrs = pdl; cfg.numAttrs = 1;
        cudaLaunchKernelEx(&cfg, ln_kernel, (const float*)y, gamma, beta, out);
    }
}

// round 16
// speedup vs baseline: 1.0036x; 1.0036x over previous
#include <cuda_runtime.h>
#include <cuda_bf16.h>
#include <cstdint>

#define BB   4
#define SS   2048
#define DD   1024
#define HH   16
#define DHH  64
#define MTOK (BB * SS)          // 8192
#define NQKV (3 * HH * DHH)     // 3072

typedef __nv_bfloat16  bf16;
typedef __nv_bfloat162 bf162;

// ---------------------------------------------------------------------------
// Scratch (static __device__ arrays; no allocation allowed)
// ---------------------------------------------------------------------------
__device__ bf16  g_inpb [(size_t)MTOK * DD];     // 16 MB
__device__ bf16  g_wqkvb[(size_t)NQKV * DD];     // 6 MB
__device__ bf16  g_wob  [(size_t)DD * DD];       // 2 MB
__device__ bf16  g_qb   [(size_t)MTOK * DD];     // 16 MB  Q projections
__device__ bf16  g_kc   [(size_t)MTOK * DD];     // 16 MB  compact K
__device__ bf16  g_vc   [(size_t)MTOK * DD];     // 16 MB  compact V
__device__ bf16  g_attnb[(size_t)MTOK * DD];     // 16 MB
__device__ float g_y    [(size_t)MTOK * DD];     // 32 MB
__device__ int   g_idx  [BB * SS];
__device__ int   g_cnt  [BB];

// ---------------------------------------------------------------------------
// Helpers: ldmatrix / mma.sync (sm_80 PTX) + cp.async + griddepcontrol
// ---------------------------------------------------------------------------
__device__ __forceinline__ uint32_t su32(const void* p) {
    return (uint32_t)__cvta_generic_to_shared(p);
}
__device__ __forceinline__ void ldm4(uint32_t& r0, uint32_t& r1, uint32_t& r2,
                                     uint32_t& r3, uint32_t a) {
    asm volatile("ldmatrix.sync.aligned.m8n8.x4.shared.b16 {%0,%1,%2,%3},[%4];\n"
                 : "=r"(r0), "=r"(r1), "=r"(r2), "=r"(r3) : "r"(a));
}
__device__ __forceinline__ void ldm4t(uint32_t& r0, uint32_t& r1, uint32_t& r2,
                                      uint32_t& r3, uint32_t a) {
    asm volatile("ldmatrix.sync.aligned.m8n8.x4.trans.shared.b16 {%0,%1,%2,%3},[%4];\n"
                 : "=r"(r0), "=r"(r1), "=r"(r2), "=r"(r3) : "r"(a));
}
__device__ __forceinline__ void mmabf(float* c, const uint32_t* a,
                                      uint32_t b0, uint32_t b1) {
    asm volatile(
        "mma.sync.aligned.m16n8k16.row.col.f32.bf16.bf16.f32 "
        "{%0,%1,%2,%3},{%4,%5,%6,%7},{%8,%9},{%0,%1,%2,%3};\n"
        : "+f"(c[0]), "+f"(c[1]), "+f"(c[2]), "+f"(c[3])
        : "r"(a[0]), "r"(a[1]), "r"(a[2]), "r"(a[3]), "r"(b0), "r"(b1));
}
__device__ __forceinline__ uint32_t packbf(float x, float y) {
    bf162 t = __floats2bfloat162_rn(x, y);
    return *reinterpret_cast<uint32_t*>(&t);
}
__device__ __forceinline__ void cpa16(uint32_t dst, const void* src) {
    asm volatile("cp.async.cg.shared.global [%0], [%1], 16;\n" :: "r"(dst), "l"(src));
}
#define CPCOMMIT() asm volatile("cp.async.commit_group;\n" ::: "memory")
#define CPWAIT(n)  asm volatile("cp.async.wait_group %0;\n" :: "n"(n) : "memory")
#define GDWAIT()   asm volatile("griddepcontrol.wait;" ::: "memory")
#define GDTRIG()   asm volatile("griddepcontrol.launch_dependents;" ::: "memory")

// ---------------------------------------------------------------------------
// Fused preprocessing: 3x f2bf + key compaction, one launch.
// ---------------------------------------------------------------------------
#define PRE_INP  (MTOK * DD / 1024)            // 8192
#define PRE_WQKV (NQKV * DD / 1024)            // 3072
#define PRE_WO   (DD * DD / 1024)              // 1024
#define PRE_TOTAL (PRE_INP + PRE_WQKV + PRE_WO + BB)

__global__ __launch_bounds__(256)
void preproc(const float* __restrict__ inp, const float* __restrict__ Wqkv,
             const float* __restrict__ Wo, const int* __restrict__ mask,
             bf16* __restrict__ inpb, bf16* __restrict__ wqkvb,
             bf16* __restrict__ wob, int* __restrict__ idx, int* __restrict__ cnt)
{
    const int bid = blockIdx.x, tid = threadIdx.x;
    if (bid < PRE_INP + PRE_WQKV + PRE_WO) {
        const float* src; bf16* dst; int blk;
        if (bid < PRE_INP)                 { src = inp;  dst = inpb;  blk = bid; }
        else if (bid < PRE_INP + PRE_WQKV) { src = Wqkv; dst = wqkvb; blk = bid - PRE_INP; }
        else                               { src = Wo;   dst = wob;   blk = bid - PRE_INP - PRE_WQKV; }
        int i = blk * 1024 + tid * 4;
        float4 v = *(const float4*)(src + i);
        bf162* o = (bf162*)(dst + i);
        o[0] = __floats2bfloat162_rn(v.x, v.y);
        o[1] = __floats2bfloat162_rn(v.z, v.w);
        GDTRIG();
        return;
    }
    // --- key compaction for batch b ---
    const int b = bid - (PRE_INP + PRE_WQKV + PRE_WO);
    const int lane = tid & 31, wid = tid >> 5;
    const int* mrow = mask + b * SS;
    __shared__ int ws[8];

    int lm[8], local = 0;
#pragma unroll
    for (int i = 0; i < 8; i++) { lm[i] = (mrow[tid * 8 + i] == 0); local += lm[i]; }

    int inc = local;
#pragma unroll
    for (int off = 1; off < 32; off <<= 1) {
        int n = __shfl_up_sync(0xffffffffu, inc, off);
        if (lane >= off) inc += n;
    }
    if (lane == 31) ws[wid] = inc;
    __syncthreads();
    if (tid == 0) {
        int run = 0;
#pragma unroll
        for (int w = 0; w < 8; w++) { int t = ws[w]; ws[w] = run; run += t; }
        cnt[b] = run;
    }
    __syncthreads();

    int pos = ws[wid] + inc - local;
#pragma unroll
    for (int i = 0; i < 8; i++)
        if (lm[i]) { idx[b * SS + pos] = tid * 8 + i; pos++; }
    GDTRIG();
}

// ---------------------------------------------------------------------------
// GEMM tiling constants: CTA 128x256, 8 warps (2Mx4N), warp tile 64x64,
// K-chunk 64, 3-stage cp.async ring in dynamic smem.
// ---------------------------------------------------------------------------
#define GLD    72
#define A_SZ   (128 * GLD)
#define B_SZ   (256 * GLD)
#define STAGE_ELEMS (A_SZ + B_SZ)
#define GSMEM_BYTES (3 * STAGE_ELEMS * 2)   // 165888

// ---------------------------------------------------------------------------
// Unified QKV GEMM (blocks [0,256): Q ; [256,768): gathered KV).
// ---------------------------------------------------------------------------
__global__ __launch_bounds__(256, 1)
void qkv_gemm(const bf16* __restrict__ inpb, const bf16* __restrict__ wqkvb,
              const float* __restrict__ bqkv, const int* __restrict__ idx,
              const int* __restrict__ cnt, bf16* __restrict__ qb,
              bf16* __restrict__ kc, bf16* __restrict__ vc)
{
    extern __shared__ __align__(16) bf16 smem[];
    __shared__ int sidx[128];

    GDWAIT();   // upstream (preproc) complete; inputs visible

    const int bid = blockIdx.x;
    const bool isQ = bid < 256;
    const int tid  = threadIdx.x;
    const int wid  = tid >> 5, lane = tid & 31;
    const int wm   = (wid >> 2) << 6;
    const int wn   = (wid & 3) << 6;
    const int r8 = tid >> 3, sg = tid & 7;

    int m0, n0, b = 0, c_ = 0;
    if (isQ) {
        n0 = (bid & 3) << 8;
        m0 = (bid >> 2) << 7;
    } else {
        const int t = bid - 256;
        b  = t >> 7;
        const int r = t & 127;
        n0 = (r & 7) << 8;
        m0 = (r >> 3) << 7;
        c_ = cnt[b];
        if (m0 >= ((c_ + 127) & ~127)) { GDTRIG(); return; }
    }

    if (tid < 128) {
        int j = m0 + tid;
        sidx[tid] = isQ ? j : ((j < c_) ? idx[b * SS + j] : 0);
    }
    __syncthreads();

    const bf16* A = inpb + (isQ ? 0 : (size_t)b * SS * DD);
    const bf16* W = wqkvb + (isQ ? 0 : (size_t)DD * DD);
    const float* bias = bqkv + (isQ ? 0 : DD);

    float acc[4][8][4];
#pragma unroll
    for (int i = 0; i < 4; i++)
#pragma unroll
        for (int j = 0; j < 8; j++)
#pragma unroll
            for (int e = 0; e < 4; e++) acc[i][j][e] = 0.0f;

    const int nk = DD >> 6;

    auto load_stage = [&](int kt) {
        bf16* As = smem + (kt % 3) * STAGE_ELEMS;
        bf16* Bs = As + A_SZ;
        const int kofs = kt << 6;
#pragma unroll
        for (int i = 0; i < 4; i++) {
            int r = r8 + i * 32;
            cpa16(su32(&As[r * GLD + sg * 8]),
                  &A[(size_t)sidx[r] * DD + kofs + sg * 8]);
        }
#pragma unroll
        for (int i = 0; i < 8; i++) {
            int r = r8 + i * 32;
            cpa16(su32(&Bs[r * GLD + sg * 8]),
                  &W[(size_t)(n0 + r) * DD + kofs + sg * 8]);
        }
        CPCOMMIT();
    };

    load_stage(0);
    load_stage(1);

    for (int kt = 0; kt < nk; kt++) {
        CPWAIT(1);
        __syncthreads();

        if (kt + 2 < nk) load_stage(kt + 2); else CPCOMMIT();

        const bf16* As = smem + (kt % 3) * STAGE_ELEMS;
        const bf16* Bs = As + A_SZ;

#pragma unroll
        for (int ks = 0; ks < 4; ks++) {
            uint32_t af[4][4], bfr[8][2];
#pragma unroll
            for (int mf = 0; mf < 4; mf++) {
                uint32_t ad = su32(&As[(wm + mf * 16 + (lane & 15)) * GLD +
                                       ks * 16 + (lane >> 4) * 8]);
                ldm4(af[mf][0], af[mf][1], af[mf][2], af[mf][3], ad);
            }
#pragma unroll
            for (int p = 0; p < 4; p++) {
                uint32_t bd = su32(&Bs[(wn + p * 16 + (lane & 7) + ((lane >> 4) << 3)) * GLD +
                                       ks * 16 + ((lane >> 3) & 1) * 8]);
                ldm4(bfr[2 * p][0], bfr[2 * p][1], bfr[2 * p + 1][0], bfr[2 * p + 1][1], bd);
            }
#pragma unroll
            for (int mf = 0; mf < 4; mf++)
#pragma unroll
                for (int nf = 0; nf < 8; nf++)
                    mmabf(acc[mf][nf], af[mf], bfr[nf][0], bfr[nf][1]);
        }
    }

    GDTRIG();   // dependents may get resident while we run the epilogue

    if (isQ) {
#pragma unroll
        for (int mf = 0; mf < 4; mf++) {
            const int r = m0 + wm + mf * 16 + (lane >> 2);
#pragma unroll
            for (int nf = 0; nf < 8; nf++) {
                const int c = n0 + wn + nf * 8 + (lane & 3) * 2;
                float b0v = bias[c], b1v = bias[c + 1];
                *(bf162*)&qb[(size_t)r * DD + c] =
                    __floats2bfloat162_rn(acc[mf][nf][0] + b0v, acc[mf][nf][1] + b1v);
                *(bf162*)&qb[(size_t)(r + 8) * DD + c] =
                    __floats2bfloat162_rn(acc[mf][nf][2] + b0v, acc[mf][nf][3] + b1v);
            }
        }
    } else {
#pragma unroll
        for (int mf = 0; mf < 4; mf++) {
            const int j = m0 + wm + mf * 16 + (lane >> 2);
#pragma unroll
            for (int nf = 0; nf < 8; nf++) {
                const int c = n0 + wn + nf * 8 + (lane & 3) * 2;
                float b0v = bias[c], b1v = bias[c + 1];
                float v0 = acc[mf][nf][0] + b0v, v1 = acc[mf][nf][1] + b1v;
                float v2 = acc[mf][nf][2] + b0v, v3 = acc[mf][nf][3] + b1v;
                if (j >= c_)     { v0 = 0.0f; v1 = 0.0f; }
                if (j + 8 >= c_) { v2 = 0.0f; v3 = 0.0f; }
                bf16* dst = (c < DD) ? kc : vc;
                const int cc = (c < DD) ? c : c - DD;
                *(bf162*)&dst[(size_t)(b * SS + j) * DD + cc]     = __floats2bfloat162_rn(v0, v1);
                *(bf162*)&dst[(size_t)(b * SS + j + 8) * DD + cc] = __floats2bfloat162_rn(v2, v3);
            }
        }
    }
}

// ---------------------------------------------------------------------------
// Out-proj GEMM (R14-measured best): CTA 128x256, warp tile 64x64, K-chunk 64,
// 3-stage cp.async ring, occupancy 1. y = attn @ Wo^T + inp (fp32 out).
// ---------------------------------------------------------------------------
__global__ __launch_bounds__(256, 1)
void hgemm_proj(const bf16* __restrict__ A, const bf16* __restrict__ W,
                const float* __restrict__ res, float* __restrict__ C,
                int M, int N, int K)
{
    extern __shared__ __align__(16) bf16 smem[];

    GDWAIT();

    const int tid  = threadIdx.x;
    const int wid  = tid >> 5, lane = tid & 31;
    const int m0   = blockIdx.y << 7;
    const int n0   = blockIdx.x << 8;
    const int wm   = (wid >> 2) << 6;
    const int wn   = (wid & 3) << 6;
    const int r8 = tid >> 3, sg = tid & 7;

    float acc[4][8][4];
#pragma unroll
    for (int i = 0; i < 4; i++)
#pragma unroll
        for (int j = 0; j < 8; j++)
#pragma unroll
            for (int e = 0; e < 4; e++) acc[i][j][e] = 0.0f;

    const int nk = K >> 6;

    auto load_stage = [&](int kt) {
        bf16* As = smem + (kt % 3) * STAGE_ELEMS;
        bf16* Bs = As + A_SZ;
        const int kofs = kt << 6;
#pragma unroll
        for (int i = 0; i < 4; i++) {
            int r = r8 + i * 32;
            cpa16(su32(&As[r * GLD + sg * 8]),
                  &A[(size_t)(m0 + r) * K + kofs + sg * 8]);
        }
#pragma unroll
        for (int i = 0; i < 8; i++) {
            int r = r8 + i * 32;
            cpa16(su32(&Bs[r * GLD + sg * 8]),
                  &W[(size_t)(n0 + r) * K + kofs + sg * 8]);
        }
        CPCOMMIT();
    };

    load_stage(0);
    load_stage(1);

    for (int kt = 0; kt < nk; kt++) {
        CPWAIT(1);
        __syncthreads();

        if (kt + 2 < nk) load_stage(kt + 2); else CPCOMMIT();

        const bf16* As = smem + (kt % 3) * STAGE_ELEMS;
        const bf16* Bs = As + A_SZ;

#pragma unroll
        for (int ks = 0; ks < 4; ks++) {
            uint32_t af[4][4], bfr[8][2];
#pragma unroll
            for (int mf = 0; mf < 4; mf++) {
                uint32_t ad = su32(&As[(wm + mf * 16 + (lane & 15)) * GLD +
                                       ks * 16 + (lane >> 4) * 8]);
                ldm4(af[mf][0], af[mf][1], af[mf][2], af[mf][3], ad);
            }
#pragma unroll
            for (int p = 0; p < 4; p++) {
                uint32_t bd = su32(&Bs[(wn + p * 16 + (lane & 7) + ((lane >> 4) << 3)) * GLD +
                                       ks * 16 + ((lane >> 3) & 1) * 8]);
                ldm4(bfr[2 * p][0], bfr[2 * p][1], bfr[2 * p + 1][0], bfr[2 * p + 1][1], bd);
            }
#pragma unroll
            for (int mf = 0; mf < 4; mf++)
#pragma unroll
                for (int nf = 0; nf < 8; nf++)
                    mmabf(acc[mf][nf], af[mf], bfr[nf][0], bfr[nf][1]);
        }
    }

    GDTRIG();

#pragma unroll
    for (int mf = 0; mf < 4; mf++) {
        const int r = m0 + wm + mf * 16 + (lane >> 2);
#pragma unroll
        for (int nf = 0; nf < 8; nf++) {
            const int c = n0 + wn + nf * 8 + (lane & 3) * 2;
            float2 q0 = *(const float2*)&res[(size_t)r * N + c];
            float2 q1 = *(const float2*)&res[(size_t)(r + 8) * N + c];
            *(float2*)&C[(size_t)r * N + c] =
                make_float2(acc[mf][nf][0] + q0.x, acc[mf][nf][1] + q0.y);
            *(float2*)&C[(size_t)(r + 8) * N + c] =
                make_float2(acc[mf][nf][2] + q1.x, acc[mf][nf][3] + q1.y);
        }
    }
}

// ---------------------------------------------------------------------------
// bf16 flash attention over COMPACTED keys (3-stage cp.async K/V ring).
// ---------------------------------------------------------------------------
#define LQT 72
#define FQ_ELEMS  (128 * LQT)
#define FKV_STAGE (2 * 64 * LQT)
#define FSMEM_BYTES ((FQ_ELEMS + 3 * FKV_STAGE) * 2)   // 73728

__global__ __launch_bounds__(256)
void flash_bf16(const bf16* __restrict__ qp, const bf16* __restrict__ kc,
                const bf16* __restrict__ vc, const int* __restrict__ cnt,
                bf16* __restrict__ attn)
{
    extern __shared__ __align__(16) bf16 fsm[];
    bf16* Qs = fsm;

    GDWAIT();

    const int tid = threadIdx.x, wid = tid >> 5, lane = tid & 31;
    const int b = blockIdx.x >> 4, h = blockIdx.x & 15;
    const int q0 = blockIdx.y << 7;

    const int c_ = cnt[b];
    const int T = ((c_ + 63) & ~63) >> 6;

    const bf16* qb  = qp + (size_t)(b * SS + q0) * DD + h * DHH;
    const bf16* kcb = kc + (size_t)b * SS * DD + h * DHH;
    const bf16* vcb = vc + (size_t)b * SS * DD + h * DHH;

    auto load_kv = [&](int t) {
        bf16* Ks = fsm + FQ_ELEMS + (t % 3) * FKV_STAGE;
        bf16* Vs = Ks + 64 * LQT;
        const int kb0 = t << 6;
#pragma unroll
        for (int i = 0; i < 2; i++) {
            int e = i * 256 + tid, r = e >> 3, sgq = e & 7;
            cpa16(su32(&Ks[r * LQT + sgq * 8]), &kcb[(size_t)(kb0 + r) * DD + sgq * 8]);
            cpa16(su32(&Vs[r * LQT + sgq * 8]), &vcb[(size_t)(kb0 + r) * DD + sgq * 8]);
        }
        CPCOMMIT();
    };

    load_kv(0);
    if (T > 1) load_kv(1); else CPCOMMIT();

#pragma unroll
    for (int i = 0; i < 4; i++) {
        int e = i * 256 + tid, r = e >> 3, sgq = e & 7;
        *(uint4*)&Qs[r * LQT + sgq * 8] = *(const uint4*)&qb[(size_t)r * DD + sgq * 8];
    }
    __syncthreads();

    uint32_t qf[4][4];
#pragma unroll
    for (int ks = 0; ks < 4; ks++) {
        uint32_t ad = su32(&Qs[(wid * 16 + (lane & 15)) * LQT + ks * 16 + (lane >> 4) * 8]);
        ldm4(qf[ks][0], qf[ks][1], qf[ks][2], qf[ks][3], ad);
    }

    float m0v = -1e30f, m1v = -1e30f, l0 = 0.0f, l1 = 0.0f;
    float o[8][4];
#pragma unroll
    for (int nf = 0; nf < 8; nf++)
#pragma unroll
        for (int e = 0; e < 4; e++) o[nf][e] = 0.0f;

    for (int t = 0; t < T; t++) {
        CPWAIT(1);
        __syncthreads();
        if (t + 2 < T) load_kv(t + 2); else CPCOMMIT();

        const bf16* Ks = fsm + FQ_ELEMS + (t % 3) * FKV_STAGE;
        const bf16* Vs = Ks + 64 * LQT;
        const int kb0 = t << 6;

        float sv[8][4];
#pragma unroll
        for (int nf = 0; nf < 8; nf++)
#pragma unroll
            for (int e = 0; e < 4; e++) sv[nf][e] = 0.0f;

#pragma unroll
        for (int ks = 0; ks < 4; ks++) {
            uint32_t kf[8][2];
#pragma unroll
            for (int p = 0; p < 4; p++) {
                uint32_t bd = su32(&Ks[(p * 16 + (lane & 7) + ((lane >> 4) << 3)) * LQT +
                                       ks * 16 + ((lane >> 3) & 1) * 8]);
                ldm4(kf[2 * p][0], kf[2 * p][1], kf[2 * p + 1][0], kf[2 * p + 1][1], bd);
            }
#pragma unroll
            for (int nf = 0; nf < 8; nf++)
                mmabf(sv[nf], qf[ks], kf[nf][0], kf[nf][1]);
        }

        const int c2 = (lane & 3) * 2;
#pragma unroll
        for (int nf = 0; nf < 8; nf++) {
            int kidx = kb0 + nf * 8 + c2;
            bool v0 = kidx < c_, v1 = (kidx + 1) < c_;
            sv[nf][0] = v0 ? sv[nf][0] * 0.125f : -1e30f;
            sv[nf][1] = v1 ? sv[nf][1] * 0.125f : -1e30f;
            sv[nf][2] = v0 ? sv[nf][2] * 0.125f : -1e30f;
            sv[nf][3] = v1 ? sv[nf][3] * 0.125f : -1e30f;
        }

        float mx0 = -1e30f, mx1 = -1e30f;
#pragma unroll
        for (int nf = 0; nf < 8; nf++) {
            mx0 = fmaxf(mx0, fmaxf(sv[nf][0], sv[nf][1]));
            mx1 = fmaxf(mx1, fmaxf(sv[nf][2], sv[nf][3]));
        }
        mx0 = fmaxf(mx0, __shfl_xor_sync(0xffffffffu, mx0, 1));
        mx0 = fmaxf(mx0, __shfl_xor_sync(0xffffffffu, mx0, 2));
        mx1 = fmaxf(mx1, __shfl_xor_sync(0xffffffffu, mx1, 1));
        mx1 = fmaxf(mx1, __shfl_xor_sync(0xffffffffu, mx1, 2));

        float mn0 = fmaxf(m0v, mx0), mn1 = fmaxf(m1v, mx1);
        float al0 = __expf(m0v - mn0), al1 = __expf(m1v - mn1);
        m0v = mn0; m1v = mn1;

        float sum0 = 0.0f, sum1 = 0.0f;
#pragma unroll
        for (int nf = 0; nf < 8; nf++) {
            sv[nf][0] = __expf(sv[nf][0] - mn0);
            sv[nf][1] = __expf(sv[nf][1] - mn0);
            sv[nf][2] = __expf(sv[nf][2] - mn1);
            sv[nf][3] = __expf(sv[nf][3] - mn1);
            sum0 += sv[nf][0] + sv[nf][1];
            sum1 += sv[nf][2] + sv[nf][3];
        }
        sum0 += __shfl_xor_sync(0xffffffffu, sum0, 1);
        sum0 += __shfl_xor_sync(0xffffffffu, sum0, 2);
        sum1 += __shfl_xor_sync(0xffffffffu, sum1, 1);
        sum1 += __shfl_xor_sync(0xffffffffu, sum1, 2);
        l0 = l0 * al0 + sum0;
        l1 = l1 * al1 + sum1;
#pragma unroll
        for (int nf = 0; nf < 8; nf++) {
            o[nf][0] *= al0; o[nf][1] *= al0;
            o[nf][2] *= al1; o[nf][3] *= al1;
        }

#pragma unroll
        for (int ks = 0; ks < 4; ks++) {
            uint32_t pa[4];
            pa[0] = packbf(sv[2 * ks][0],     sv[2 * ks][1]);
            pa[1] = packbf(sv[2 * ks][2],     sv[2 * ks][3]);
            pa[2] = packbf(sv[2 * ks + 1][0], sv[2 * ks + 1][1]);
            pa[3] = packbf(sv[2 * ks + 1][2], sv[2 * ks + 1][3]);
#pragma unroll
            for (int p = 0; p < 4; p++) {
                uint32_t v0, v1, v2, v3;
                uint32_t vd = su32(&Vs[(ks * 16 + (lane & 7) + (((lane >> 3) & 1) << 3)) * LQT +
                                       p * 16 + ((lane >> 4) << 3)]);
                ldm4t(v0, v1, v2, v3, vd);
                mmabf(o[2 * p],     pa, v0, v1);
                mmabf(o[2 * p + 1], pa, v2, v3);
            }
        }
    }

    GDTRIG();

    const float i0 = 1.0f / l0, i1 = 1.0f / l1;
    const int r0 = q0 + wid * 16 + (lane >> 2);
    bf16* ob = attn + (size_t)b * SS * DD + h * DHH;
#pragma unroll
    for (int nf = 0; nf < 8; nf++) {
        int c = nf * 8 + (lane & 3) * 2;
        *(bf162*)&ob[(size_t)r0 * DD + c] =
            __floats2bfloat162_rn(o[nf][0] * i0, o[nf][1] * i0);
        *(bf162*)&ob[(size_t)(r0 + 8) * DD + c] =
            __floats2bfloat162_rn(o[nf][2] * i1, o[nf][3] * i1);
    }
}

// ---------------------------------------------------------------------------
// LayerNorm: one WARP per row (8 rows/block).
// ---------------------------------------------------------------------------
__global__ __launch_bounds__(256)
void ln_kernel(const float* __restrict__ y, const float* __restrict__ gamma,
               const float* __restrict__ beta, float* __restrict__ out)
{
    GDWAIT();

    const int wid = threadIdx.x >> 5, lane = threadIdx.x & 31;
    const int row = blockIdx.x * 8 + wid;
    const float* yr = y + (size_t)row * DD;

    float4 v[8];
    float s = 0.0f, s2 = 0.0f;
#pragma unroll
    for (int i = 0; i < 8; i++) {
        v[i] = *(const float4*)&yr[lane * 4 + i * 128];
        s  += v[i].x + v[i].y + v[i].z + v[i].w;
        s2 += v[i].x * v[i].x + v[i].y * v[i].y + v[i].z * v[i].z + v[i].w * v[i].w;
    }
#pragma unroll
    for (int off = 16; off; off >>= 1) {
        s  += __shfl_xor_sync(0xffffffffu, s,  off);
        s2 += __shfl_xor_sync(0xffffffffu, s2, off);
    }

    const float mean = s * (1.0f / DD);
    const float var  = s2 * (1.0f / DD) - mean * mean;
    const float inv  = rsqrtf(var + 1e-5f);

#pragma unroll
    for (int i = 0; i < 8; i++) {
        const int c = lane * 4 + i * 128;
        float4 g  = *(const float4*)&gamma[c];
        float4 bt = *(const float4*)&beta[c];
        float4 r;
        r.x = (v[i].x - mean) * inv * g.x + bt.x;
        r.y = (v[i].y - mean) * inv * g.y + bt.y;
        r.z = (v[i].z - mean) * inv * g.z + bt.z;
        r.w = (v[i].w - mean) * inv * g.w + bt.w;
        *(float4*)&out[(size_t)row * DD + c] = r;
    }
}

// ---------------------------------------------------------------------------
extern "C" void kernel_launch(void* const* d_in, const int* in_sizes, int n_in,
                              void* d_out, int out_size)
{
    (void)in_sizes; (void)n_in; (void)out_size;
    const float* inp   = (const float*)d_in[0];
    const int*   mask  = (const int*)d_in[1];
    const float* Wqkv  = (const float*)d_in[2];
    const float* bqkv  = (const float*)d_in[3];
    const float* Wo    = (const float*)d_in[4];
    const float* gamma = (const float*)d_in[5];
    const float* beta  = (const float*)d_in[6];
    float* out = (float*)d_out;

    bf16 *inpb, *wqkvb, *wob, *qb, *kc, *vc, *attnb;
    float* y;
    int *idx, *cnt;
    cudaGetSymbolAddress((void**)&inpb,  g_inpb);
    cudaGetSymbolAddress((void**)&wqkvb, g_wqkvb);
    cudaGetSymbolAddress((void**)&wob,   g_wob);
    cudaGetSymbolAddress((void**)&qb,    g_qb);
    cudaGetSymbolAddress((void**)&kc,    g_kc);
    cudaGetSymbolAddress((void**)&vc,    g_vc);
    cudaGetSymbolAddress((void**)&attnb, g_attnb);
    cudaGetSymbolAddress((void**)&y,     g_y);
    cudaGetSymbolAddress((void**)&idx,   g_idx);
    cudaGetSymbolAddress((void**)&cnt,   g_cnt);

    cudaFuncSetAttribute(qkv_gemm,
                         cudaFuncAttributeMaxDynamicSharedMemorySize, GSMEM_BYTES);
    cudaFuncSetAttribute(hgemm_proj,
                         cudaFuncAttributeMaxDynamicSharedMemorySize, GSMEM_BYTES);
    cudaFuncSetAttribute(flash_bf16,
                         cudaFuncAttributeMaxDynamicSharedMemorySize, FSMEM_BYTES);

    // PDL launch attribute (dependent may start during predecessor's epilogue)
    cudaLaunchAttribute pdl[1];
    pdl[0].id = cudaLaunchAttributeProgrammaticStreamSerialization;
    pdl[0].val.programmaticStreamSerializationAllowed = 1;

    // 0) fused conversions + key compaction
    preproc<<<PRE_TOTAL, 256>>>(inp, Wqkv, Wo, mask, inpb, wqkvb, wob, idx, cnt);

    // 1) unified Q + gathered-KV GEMM
    {
        cudaLaunchConfig_t cfg = {};
        cfg.gridDim = dim3(768, 1, 1); cfg.blockDim = dim3(256, 1, 1);
        cfg.dynamicSmemBytes = GSMEM_BYTES; cfg.stream = 0;
        cfg.attrs = pdl; cfg.numAttrs = 1;
        cudaLaunchKernelEx(&cfg, qkv_gemm, inpb, wqkvb, bqkv,
                           (const int*)idx, (const int*)cnt, qb, kc, vc);
    }

    // 2) attention over ~cnt keys
    {
        cudaLaunchConfig_t cfg = {};
        cfg.gridDim = dim3(BB * HH, SS / 128, 1); cfg.blockDim = dim3(256, 1, 1);
        cfg.dynamicSmemBytes = FSMEM_BYTES; cfg.stream = 0;
        cfg.attrs = pdl; cfg.numAttrs = 1;
        cudaLaunchKernelEx(&cfg, flash_bf16, (const bf16*)qb, (const bf16*)kc,
                           (const bf16*)vc, (const int*)cnt, attnb);
    }

    // 3) y = inp + attn @ Wo^T  (128x256 tile, occupancy-1: measured best)
    {
        cudaLaunchConfig_t cfg = {};
        cfg.gridDim = dim3(DD / 256, MTOK / 128, 1); cfg.blockDim = dim3(256, 1, 1);
        cfg.dynamicSmemBytes = GSMEM_BYTES; cfg.stream = 0;
        cfg.attrs = pdl; cfg.numAttrs = 1;
        cudaLaunchKernelEx(&cfg, hgemm_proj, (const bf16*)attnb, (const bf16*)wob,
                           inp, y, MTOK, DD, DD);
    }

    // 4) out = LayerNorm(y)
    {
        cudaLaunchConfig_t cfg = {};
        cfg.gridDim = dim3(MTOK / 8, 1, 1); cfg.blockDim = dim3(256, 1, 1);
        cfg.dynamicSmemBytes = 0; cfg.stream = 0;
        cfg.attrs = pdl; cfg.numAttrs = 1;
        cudaLaunchKernelEx(&cfg, ln_kernel, (const float*)y, gamma, beta, out);
    }
}

// round 17
// speedup vs baseline: 1.0197x; 1.0160x over previous
#include <cuda_runtime.h>
#include <cuda_bf16.h>
#include <cstdint>

#define BB   4
#define SS   2048
#define DD   1024
#define HH   16
#define DHH  64
#define MTOK (BB * SS)          // 8192
#define NQKV (3 * HH * DHH)     // 3072

typedef __nv_bfloat16  bf16;
typedef __nv_bfloat162 bf162;

// ---------------------------------------------------------------------------
// Scratch (static __device__ arrays; no allocation allowed)
// ---------------------------------------------------------------------------
__device__ bf16  g_inpb [(size_t)MTOK * DD];     // 16 MB
__device__ bf16  g_wqkvb[(size_t)NQKV * DD];     // 6 MB
__device__ bf16  g_wob  [(size_t)DD * DD];       // 2 MB
__device__ bf16  g_qb   [(size_t)MTOK * DD];     // 16 MB  Q projections
__device__ bf16  g_kc   [(size_t)MTOK * DD];     // 16 MB  compact K
__device__ bf16  g_vc   [(size_t)MTOK * DD];     // 16 MB  compact V
__device__ bf16  g_attnb[(size_t)MTOK * DD];     // 16 MB
__device__ float g_y    [(size_t)MTOK * DD];     // 32 MB
__device__ int   g_idx  [BB * SS];
__device__ int   g_cnt  [BB];

// ---------------------------------------------------------------------------
// Helpers: ldmatrix / mma.sync (sm_80 PTX) + cp.async + griddepcontrol
// ---------------------------------------------------------------------------
__device__ __forceinline__ uint32_t su32(const void* p) {
    return (uint32_t)__cvta_generic_to_shared(p);
}
__device__ __forceinline__ void ldm4(uint32_t& r0, uint32_t& r1, uint32_t& r2,
                                     uint32_t& r3, uint32_t a) {
    asm volatile("ldmatrix.sync.aligned.m8n8.x4.shared.b16 {%0,%1,%2,%3},[%4];\n"
                 : "=r"(r0), "=r"(r1), "=r"(r2), "=r"(r3) : "r"(a));
}
__device__ __forceinline__ void ldm4t(uint32_t& r0, uint32_t& r1, uint32_t& r2,
                                      uint32_t& r3, uint32_t a) {
    asm volatile("ldmatrix.sync.aligned.m8n8.x4.trans.shared.b16 {%0,%1,%2,%3},[%4];\n"
                 : "=r"(r0), "=r"(r1), "=r"(r2), "=r"(r3) : "r"(a));
}
__device__ __forceinline__ void mmabf(float* c, const uint32_t* a,
                                      uint32_t b0, uint32_t b1) {
    asm volatile(
        "mma.sync.aligned.m16n8k16.row.col.f32.bf16.bf16.f32 "
        "{%0,%1,%2,%3},{%4,%5,%6,%7},{%8,%9},{%0,%1,%2,%3};\n"
        : "+f"(c[0]), "+f"(c[1]), "+f"(c[2]), "+f"(c[3])
        : "r"(a[0]), "r"(a[1]), "r"(a[2]), "r"(a[3]), "r"(b0), "r"(b1));
}
__device__ __forceinline__ uint32_t packbf(float x, float y) {
    bf162 t = __floats2bfloat162_rn(x, y);
    return *reinterpret_cast<uint32_t*>(&t);
}
__device__ __forceinline__ void cpa16(uint32_t dst, const void* src) {
    asm volatile("cp.async.cg.shared.global [%0], [%1], 16;\n" :: "r"(dst), "l"(src));
}
#define CPCOMMIT() asm volatile("cp.async.commit_group;\n" ::: "memory")
#define CPWAIT(n)  asm volatile("cp.async.wait_group %0;\n" :: "n"(n) : "memory")
#define GDWAIT()   asm volatile("griddepcontrol.wait;" ::: "memory")
#define GDTRIG()   asm volatile("griddepcontrol.launch_dependents;" ::: "memory")

// ---------------------------------------------------------------------------
// Fused preprocessing: 3x f2bf + key compaction, one launch.
// ---------------------------------------------------------------------------
#define PRE_INP  (MTOK * DD / 1024)            // 8192
#define PRE_WQKV (NQKV * DD / 1024)            // 3072
#define PRE_WO   (DD * DD / 1024)              // 1024
#define PRE_TOTAL (PRE_INP + PRE_WQKV + PRE_WO + BB)

__global__ __launch_bounds__(256)
void preproc(const float* __restrict__ inp, const float* __restrict__ Wqkv,
             const float* __restrict__ Wo, const int* __restrict__ mask,
             bf16* __restrict__ inpb, bf16* __restrict__ wqkvb,
             bf16* __restrict__ wob, int* __restrict__ idx, int* __restrict__ cnt)
{
    const int bid = blockIdx.x, tid = threadIdx.x;
    if (bid < PRE_INP + PRE_WQKV + PRE_WO) {
        const float* src; bf16* dst; int blk;
        if (bid < PRE_INP)                 { src = inp;  dst = inpb;  blk = bid; }
        else if (bid < PRE_INP + PRE_WQKV) { src = Wqkv; dst = wqkvb; blk = bid - PRE_INP; }
        else                               { src = Wo;   dst = wob;   blk = bid - PRE_INP - PRE_WQKV; }
        int i = blk * 1024 + tid * 4;
        float4 v = *(const float4*)(src + i);
        bf162* o = (bf162*)(dst + i);
        o[0] = __floats2bfloat162_rn(v.x, v.y);
        o[1] = __floats2bfloat162_rn(v.z, v.w);
        GDTRIG();
        return;
    }
    // --- key compaction for batch b ---
    const int b = bid - (PRE_INP + PRE_WQKV + PRE_WO);
    const int lane = tid & 31, wid = tid >> 5;
    const int* mrow = mask + b * SS;
    __shared__ int ws[8];

    int lm[8], local = 0;
#pragma unroll
    for (int i = 0; i < 8; i++) { lm[i] = (mrow[tid * 8 + i] == 0); local += lm[i]; }

    int inc = local;
#pragma unroll
    for (int off = 1; off < 32; off <<= 1) {
        int n = __shfl_up_sync(0xffffffffu, inc, off);
        if (lane >= off) inc += n;
    }
    if (lane == 31) ws[wid] = inc;
    __syncthreads();
    if (tid == 0) {
        int run = 0;
#pragma unroll
        for (int w = 0; w < 8; w++) { int t = ws[w]; ws[w] = run; run += t; }
        cnt[b] = run;
    }
    __syncthreads();

    int pos = ws[wid] + inc - local;
#pragma unroll
    for (int i = 0; i < 8; i++)
        if (lm[i]) { idx[b * SS + pos] = tid * 8 + i; pos++; }
    GDTRIG();
}

// ---------------------------------------------------------------------------
// GEMM tiling constants: CTA 128x256, 8 warps (2Mx4N), warp tile 64x64,
// K-chunk 64, 3-stage cp.async ring in dynamic smem.
// ---------------------------------------------------------------------------
#define GLD    72
#define A_SZ   (128 * GLD)
#define B_SZ   (256 * GLD)
#define STAGE_ELEMS (A_SZ + B_SZ)
#define GSMEM_BYTES (3 * STAGE_ELEMS * 2)   // 165888

// ---------------------------------------------------------------------------
// Unified QKV GEMM (blocks [0,256): Q ; [256,768): gathered KV).
// ---------------------------------------------------------------------------
__global__ __launch_bounds__(256, 1)
void qkv_gemm(const bf16* __restrict__ inpb, const bf16* __restrict__ wqkvb,
              const float* __restrict__ bqkv, const int* __restrict__ idx,
              const int* __restrict__ cnt, bf16* __restrict__ qb,
              bf16* __restrict__ kc, bf16* __restrict__ vc)
{
    extern __shared__ __align__(16) bf16 smem[];
    __shared__ int sidx[128];

    GDWAIT();   // upstream (preproc) complete; inputs visible

    const int bid = blockIdx.x;
    const bool isQ = bid < 256;
    const int tid  = threadIdx.x;
    const int wid  = tid >> 5, lane = tid & 31;
    const int wm   = (wid >> 2) << 6;
    const int wn   = (wid & 3) << 6;
    const int r8 = tid >> 3, sg = tid & 7;

    int m0, n0, b = 0, c_ = 0;
    if (isQ) {
        n0 = (bid & 3) << 8;
        m0 = (bid >> 2) << 7;
    } else {
        const int t = bid - 256;
        b  = t >> 7;
        const int r = t & 127;
        n0 = (r & 7) << 8;
        m0 = (r >> 3) << 7;
        c_ = cnt[b];
        if (m0 >= ((c_ + 127) & ~127)) { GDTRIG(); return; }
    }

    if (tid < 128) {
        int j = m0 + tid;
        sidx[tid] = isQ ? j : ((j < c_) ? idx[b * SS + j] : 0);
    }
    __syncthreads();

    const bf16* A = inpb + (isQ ? 0 : (size_t)b * SS * DD);
    const bf16* W = wqkvb + (isQ ? 0 : (size_t)DD * DD);
    const float* bias = bqkv + (isQ ? 0 : DD);

    float acc[4][8][4];
#pragma unroll
    for (int i = 0; i < 4; i++)
#pragma unroll
        for (int j = 0; j < 8; j++)
#pragma unroll
            for (int e = 0; e < 4; e++) acc[i][j][e] = 0.0f;

    const int nk = DD >> 6;

    auto load_stage = [&](int kt) {
        bf16* As = smem + (kt % 3) * STAGE_ELEMS;
        bf16* Bs = As + A_SZ;
        const int kofs = kt << 6;
#pragma unroll
        for (int i = 0; i < 4; i++) {
            int r = r8 + i * 32;
            cpa16(su32(&As[r * GLD + sg * 8]),
                  &A[(size_t)sidx[r] * DD + kofs + sg * 8]);
        }
#pragma unroll
        for (int i = 0; i < 8; i++) {
            int r = r8 + i * 32;
            cpa16(su32(&Bs[r * GLD + sg * 8]),
                  &W[(size_t)(n0 + r) * DD + kofs + sg * 8]);
        }
        CPCOMMIT();
    };

    load_stage(0);
    load_stage(1);

    for (int kt = 0; kt < nk; kt++) {
        CPWAIT(1);
        __syncthreads();

        if (kt + 2 < nk) load_stage(kt + 2); else CPCOMMIT();

        const bf16* As = smem + (kt % 3) * STAGE_ELEMS;
        const bf16* Bs = As + A_SZ;

#pragma unroll
        for (int ks = 0; ks < 4; ks++) {
            uint32_t af[4][4], bfr[8][2];
#pragma unroll
            for (int mf = 0; mf < 4; mf++) {
                uint32_t ad = su32(&As[(wm + mf * 16 + (lane & 15)) * GLD +
                                       ks * 16 + (lane >> 4) * 8]);
                ldm4(af[mf][0], af[mf][1], af[mf][2], af[mf][3], ad);
            }
#pragma unroll
            for (int p = 0; p < 4; p++) {
                uint32_t bd = su32(&Bs[(wn + p * 16 + (lane & 7) + ((lane >> 4) << 3)) * GLD +
                                       ks * 16 + ((lane >> 3) & 1) * 8]);
                ldm4(bfr[2 * p][0], bfr[2 * p][1], bfr[2 * p + 1][0], bfr[2 * p + 1][1], bd);
            }
#pragma unroll
            for (int mf = 0; mf < 4; mf++)
#pragma unroll
                for (int nf = 0; nf < 8; nf++)
                    mmabf(acc[mf][nf], af[mf], bfr[nf][0], bfr[nf][1]);
        }
    }

    GDTRIG();   // dependents may get resident while we run the epilogue

    if (isQ) {
#pragma unroll
        for (int mf = 0; mf < 4; mf++) {
            const int r = m0 + wm + mf * 16 + (lane >> 2);
#pragma unroll
            for (int nf = 0; nf < 8; nf++) {
                const int c = n0 + wn + nf * 8 + (lane & 3) * 2;
                float b0v = bias[c], b1v = bias[c + 1];
                *(bf162*)&qb[(size_t)r * DD + c] =
                    __floats2bfloat162_rn(acc[mf][nf][0] + b0v, acc[mf][nf][1] + b1v);
                *(bf162*)&qb[(size_t)(r + 8) * DD + c] =
                    __floats2bfloat162_rn(acc[mf][nf][2] + b0v, acc[mf][nf][3] + b1v);
            }
        }
    } else {
#pragma unroll
        for (int mf = 0; mf < 4; mf++) {
            const int j = m0 + wm + mf * 16 + (lane >> 2);
#pragma unroll
            for (int nf = 0; nf < 8; nf++) {
                const int c = n0 + wn + nf * 8 + (lane & 3) * 2;
                float b0v = bias[c], b1v = bias[c + 1];
                float v0 = acc[mf][nf][0] + b0v, v1 = acc[mf][nf][1] + b1v;
                float v2 = acc[mf][nf][2] + b0v, v3 = acc[mf][nf][3] + b1v;
                if (j >= c_)     { v0 = 0.0f; v1 = 0.0f; }
                if (j + 8 >= c_) { v2 = 0.0f; v3 = 0.0f; }
                bf16* dst = (c < DD) ? kc : vc;
                const int cc = (c < DD) ? c : c - DD;
                *(bf162*)&dst[(size_t)(b * SS + j) * DD + cc]     = __floats2bfloat162_rn(v0, v1);
                *(bf162*)&dst[(size_t)(b * SS + j + 8) * DD + cc] = __floats2bfloat162_rn(v2, v3);
            }
        }
    }
}

// ---------------------------------------------------------------------------
// Out-proj GEMM (R14-measured best): CTA 128x256, warp tile 64x64, K-chunk 64,
// 3-stage cp.async ring, occupancy 1. y = attn @ Wo^T + inp (fp32 out).
// ---------------------------------------------------------------------------
__global__ __launch_bounds__(256, 1)
void hgemm_proj(const bf16* __restrict__ A, const bf16* __restrict__ W,
                const float* __restrict__ res, float* __restrict__ C,
                int M, int N, int K)
{
    extern __shared__ __align__(16) bf16 smem[];

    GDWAIT();

    const int tid  = threadIdx.x;
    const int wid  = tid >> 5, lane = tid & 31;
    const int m0   = blockIdx.y << 7;
    const int n0   = blockIdx.x << 8;
    const int wm   = (wid >> 2) << 6;
    const int wn   = (wid & 3) << 6;
    const int r8 = tid >> 3, sg = tid & 7;

    float acc[4][8][4];
#pragma unroll
    for (int i = 0; i < 4; i++)
#pragma unroll
        for (int j = 0; j < 8; j++)
#pragma unroll
            for (int e = 0; e < 4; e++) acc[i][j][e] = 0.0f;

    const int nk = K >> 6;

    auto load_stage = [&](int kt) {
        bf16* As = smem + (kt % 3) * STAGE_ELEMS;
        bf16* Bs = As + A_SZ;
        const int kofs = kt << 6;
#pragma unroll
        for (int i = 0; i < 4; i++) {
            int r = r8 + i * 32;
            cpa16(su32(&As[r * GLD + sg * 8]),
                  &A[(size_t)(m0 + r) * K + kofs + sg * 8]);
        }
#pragma unroll
        for (int i = 0; i < 8; i++) {
            int r = r8 + i * 32;
            cpa16(su32(&Bs[r * GLD + sg * 8]),
                  &W[(size_t)(n0 + r) * K + kofs + sg * 8]);
        }
        CPCOMMIT();
    };

    load_stage(0);
    load_stage(1);

    for (int kt = 0; kt < nk; kt++) {
        CPWAIT(1);
        __syncthreads();

        if (kt + 2 < nk) load_stage(kt + 2); else CPCOMMIT();

        const bf16* As = smem + (kt % 3) * STAGE_ELEMS;
        const bf16* Bs = As + A_SZ;

#pragma unroll
        for (int ks = 0; ks < 4; ks++) {
            uint32_t af[4][4], bfr[8][2];
#pragma unroll
            for (int mf = 0; mf < 4; mf++) {
                uint32_t ad = su32(&As[(wm + mf * 16 + (lane & 15)) * GLD +
                                       ks * 16 + (lane >> 4) * 8]);
                ldm4(af[mf][0], af[mf][1], af[mf][2], af[mf][3], ad);
            }
#pragma unroll
            for (int p = 0; p < 4; p++) {
                uint32_t bd = su32(&Bs[(wn + p * 16 + (lane & 7) + ((lane >> 4) << 3)) * GLD +
                                       ks * 16 + ((lane >> 3) & 1) * 8]);
                ldm4(bfr[2 * p][0], bfr[2 * p][1], bfr[2 * p + 1][0], bfr[2 * p + 1][1], bd);
            }
#pragma unroll
            for (int mf = 0; mf < 4; mf++)
#pragma unroll
                for (int nf = 0; nf < 8; nf++)
                    mmabf(acc[mf][nf], af[mf], bfr[nf][0], bfr[nf][1]);
        }
    }

    GDTRIG();

#pragma unroll
    for (int mf = 0; mf < 4; mf++) {
        const int r = m0 + wm + mf * 16 + (lane >> 2);
#pragma unroll
        for (int nf = 0; nf < 8; nf++) {
            const int c = n0 + wn + nf * 8 + (lane & 3) * 2;
            float2 q0 = *(const float2*)&res[(size_t)r * N + c];
            float2 q1 = *(const float2*)&res[(size_t)(r + 8) * N + c];
            *(float2*)&C[(size_t)r * N + c] =
                make_float2(acc[mf][nf][0] + q0.x, acc[mf][nf][1] + q0.y);
            *(float2*)&C[(size_t)(r + 8) * N + c] =
                make_float2(acc[mf][nf][2] + q1.x, acc[mf][nf][3] + q1.y);
        }
    }
}

// ---------------------------------------------------------------------------
// bf16 flash attention over COMPACTED keys (3-stage cp.async K/V ring).
// Softmax in base-2 domain: scores scaled by 0.125*log2(e); exp2f replaces
// __expf (drops the hidden x*log2e FMUL per exp). Probabilities identical.
// ---------------------------------------------------------------------------
#define LQT 72
#define FQ_ELEMS  (128 * LQT)
#define FKV_STAGE (2 * 64 * LQT)
#define FSMEM_BYTES ((FQ_ELEMS + 3 * FKV_STAGE) * 2)   // 73728
#define SCALE2 0.18033688f   // 0.125 * log2(e)

__global__ __launch_bounds__(256)
void flash_bf16(const bf16* __restrict__ qp, const bf16* __restrict__ kc,
                const bf16* __restrict__ vc, const int* __restrict__ cnt,
                bf16* __restrict__ attn)
{
    extern __shared__ __align__(16) bf16 fsm[];
    bf16* Qs = fsm;

    GDWAIT();

    const int tid = threadIdx.x, wid = tid >> 5, lane = tid & 31;
    const int b = blockIdx.x >> 4, h = blockIdx.x & 15;
    const int q0 = blockIdx.y << 7;

    const int c_ = cnt[b];
    const int T = ((c_ + 63) & ~63) >> 6;

    const bf16* qb  = qp + (size_t)(b * SS + q0) * DD + h * DHH;
    const bf16* kcb = kc + (size_t)b * SS * DD + h * DHH;
    const bf16* vcb = vc + (size_t)b * SS * DD + h * DHH;

    auto load_kv = [&](int t) {
        bf16* Ks = fsm + FQ_ELEMS + (t % 3) * FKV_STAGE;
        bf16* Vs = Ks + 64 * LQT;
        const int kb0 = t << 6;
#pragma unroll
        for (int i = 0; i < 2; i++) {
            int e = i * 256 + tid, r = e >> 3, sgq = e & 7;
            cpa16(su32(&Ks[r * LQT + sgq * 8]), &kcb[(size_t)(kb0 + r) * DD + sgq * 8]);
            cpa16(su32(&Vs[r * LQT + sgq * 8]), &vcb[(size_t)(kb0 + r) * DD + sgq * 8]);
        }
        CPCOMMIT();
    };

    load_kv(0);
    if (T > 1) load_kv(1); else CPCOMMIT();

#pragma unroll
    for (int i = 0; i < 4; i++) {
        int e = i * 256 + tid, r = e >> 3, sgq = e & 7;
        *(uint4*)&Qs[r * LQT + sgq * 8] = *(const uint4*)&qb[(size_t)r * DD + sgq * 8];
    }
    __syncthreads();

    uint32_t qf[4][4];
#pragma unroll
    for (int ks = 0; ks < 4; ks++) {
        uint32_t ad = su32(&Qs[(wid * 16 + (lane & 15)) * LQT + ks * 16 + (lane >> 4) * 8]);
        ldm4(qf[ks][0], qf[ks][1], qf[ks][2], qf[ks][3], ad);
    }

    float m0v = -1e30f, m1v = -1e30f, l0 = 0.0f, l1 = 0.0f;
    float o[8][4];
#pragma unroll
    for (int nf = 0; nf < 8; nf++)
#pragma unroll
        for (int e = 0; e < 4; e++) o[nf][e] = 0.0f;

    for (int t = 0; t < T; t++) {
        CPWAIT(1);
        __syncthreads();
        if (t + 2 < T) load_kv(t + 2); else CPCOMMIT();

        const bf16* Ks = fsm + FQ_ELEMS + (t % 3) * FKV_STAGE;
        const bf16* Vs = Ks + 64 * LQT;
        const int kb0 = t << 6;

        float sv[8][4];
#pragma unroll
        for (int nf = 0; nf < 8; nf++)
#pragma unroll
            for (int e = 0; e < 4; e++) sv[nf][e] = 0.0f;

#pragma unroll
        for (int ks = 0; ks < 4; ks++) {
            uint32_t kf[8][2];
#pragma unroll
            for (int p = 0; p < 4; p++) {
                uint32_t bd = su32(&Ks[(p * 16 + (lane & 7) + ((lane >> 4) << 3)) * LQT +
                                       ks * 16 + ((lane >> 3) & 1) * 8]);
                ldm4(kf[2 * p][0], kf[2 * p][1], kf[2 * p + 1][0], kf[2 * p + 1][1], bd);
            }
#pragma unroll
            for (int nf = 0; nf < 8; nf++)
                mmabf(sv[nf], qf[ks], kf[nf][0], kf[nf][1]);
        }

        // scale into base-2 domain + tail validity (key slot >= cnt -> -1e30)
        const int c2 = (lane & 3) * 2;
#pragma unroll
        for (int nf = 0; nf < 8; nf++) {
            int kidx = kb0 + nf * 8 + c2;
            bool v0 = kidx < c_, v1 = (kidx + 1) < c_;
            sv[nf][0] = v0 ? sv[nf][0] * SCALE2 : -1e30f;
            sv[nf][1] = v1 ? sv[nf][1] * SCALE2 : -1e30f;
            sv[nf][2] = v0 ? sv[nf][2] * SCALE2 : -1e30f;
            sv[nf][3] = v1 ? sv[nf][3] * SCALE2 : -1e30f;
        }

        float mx0 = -1e30f, mx1 = -1e30f;
#pragma unroll
        for (int nf = 0; nf < 8; nf++) {
            mx0 = fmaxf(mx0, fmaxf(sv[nf][0], sv[nf][1]));
            mx1 = fmaxf(mx1, fmaxf(sv[nf][2], sv[nf][3]));
        }
        mx0 = fmaxf(mx0, __shfl_xor_sync(0xffffffffu, mx0, 1));
        mx0 = fmaxf(mx0, __shfl_xor_sync(0xffffffffu, mx0, 2));
        mx1 = fmaxf(mx1, __shfl_xor_sync(0xffffffffu, mx1, 1));
        mx1 = fmaxf(mx1, __shfl_xor_sync(0xffffffffu, mx1, 2));

        float mn0 = fmaxf(m0v, mx0), mn1 = fmaxf(m1v, mx1);
        float al0 = exp2f(m0v - mn0), al1 = exp2f(m1v - mn1);
        m0v = mn0; m1v = mn1;

        float sum0 = 0.0f, sum1 = 0.0f;
#pragma unroll
        for (int nf = 0; nf < 8; nf++) {
            sv[nf][0] = exp2f(sv[nf][0] - mn0);
            sv[nf][1] = exp2f(sv[nf][1] - mn0);
            sv[nf][2] = exp2f(sv[nf][2] - mn1);
            sv[nf][3] = exp2f(sv[nf][3] - mn1);
            sum0 += sv[nf][0] + sv[nf][1];
            sum1 += sv[nf][2] + sv[nf][3];
        }
        sum0 += __shfl_xor_sync(0xffffffffu, sum0, 1);
        sum0 += __shfl_xor_sync(0xffffffffu, sum0, 2);
        sum1 += __shfl_xor_sync(0xffffffffu, sum1, 1);
        sum1 += __shfl_xor_sync(0xffffffffu, sum1, 2);
        l0 = l0 * al0 + sum0;
        l1 = l1 * al1 + sum1;
#pragma unroll
        for (int nf = 0; nf < 8; nf++) {
            o[nf][0] *= al0; o[nf][1] *= al0;
            o[nf][2] *= al1; o[nf][3] *= al1;
        }

#pragma unroll
        for (int ks = 0; ks < 4; ks++) {
            uint32_t pa[4];
            pa[0] = packbf(sv[2 * ks][0],     sv[2 * ks][1]);
            pa[1] = packbf(sv[2 * ks][2],     sv[2 * ks][3]);
            pa[2] = packbf(sv[2 * ks + 1][0], sv[2 * ks + 1][1]);
            pa[3] = packbf(sv[2 * ks + 1][2], sv[2 * ks + 1][3]);
#pragma unroll
            for (int p = 0; p < 4; p++) {
                uint32_t v0, v1, v2, v3;
                uint32_t vd = su32(&Vs[(ks * 16 + (lane & 7) + (((lane >> 3) & 1) << 3)) * LQT +
                                       p * 16 + ((lane >> 4) << 3)]);
                ldm4t(v0, v1, v2, v3, vd);
                mmabf(o[2 * p],     pa, v0, v1);
                mmabf(o[2 * p + 1], pa, v2, v3);
            }
        }
    }

    GDTRIG();

    const float i0 = 1.0f / l0, i1 = 1.0f / l1;
    const int r0 = q0 + wid * 16 + (lane >> 2);
    bf16* ob = attn + (size_t)b * SS * DD + h * DHH;
#pragma unroll
    for (int nf = 0; nf < 8; nf++) {
        int c = nf * 8 + (lane & 3) * 2;
        *(bf162*)&ob[(size_t)r0 * DD + c] =
            __floats2bfloat162_rn(o[nf][0] * i0, o[nf][1] * i0);
        *(bf162*)&ob[(size_t)(r0 + 8) * DD + c] =
            __floats2bfloat162_rn(o[nf][2] * i1, o[nf][3] * i1);
    }
}

// ---------------------------------------------------------------------------
// LayerNorm: one WARP per row (8 rows/block).
// ---------------------------------------------------------------------------
__global__ __launch_bounds__(256)
void ln_kernel(const float* __restrict__ y, const float* __restrict__ gamma,
               const float* __restrict__ beta, float* __restrict__ out)
{
    GDWAIT();

    const int wid = threadIdx.x >> 5, lane = threadIdx.x & 31;
    const int row = blockIdx.x * 8 + wid;
    const float* yr = y + (size_t)row * DD;

    float4 v[8];
    float s = 0.0f, s2 = 0.0f;
#pragma unroll
    for (int i = 0; i < 8; i++) {
        v[i] = *(const float4*)&yr[lane * 4 + i * 128];
        s  += v[i].x + v[i].y + v[i].z + v[i].w;
        s2 += v[i].x * v[i].x + v[i].y * v[i].y + v[i].z * v[i].z + v[i].w * v[i].w;
    }
#pragma unroll
    for (int off = 16; off; off >>= 1) {
        s  += __shfl_xor_sync(0xffffffffu, s,  off);
        s2 += __shfl_xor_sync(0xffffffffu, s2, off);
    }

    const float mean = s * (1.0f / DD);
    const float var  = s2 * (1.0f / DD) - mean * mean;
    const float inv  = rsqrtf(var + 1e-5f);

#pragma unroll
    for (int i = 0; i < 8; i++) {
        const int c = lane * 4 + i * 128;
        float4 g  = *(const float4*)&gamma[c];
        float4 bt = *(const float4*)&beta[c];
        float4 r;
        r.x = (v[i].x - mean) * inv * g.x + bt.x;
        r.y = (v[i].y - mean) * inv * g.y + bt.y;
        r.z = (v[i].z - mean) * inv * g.z + bt.z;
        r.w = (v[i].w - mean) * inv * g.w + bt.w;
        *(float4*)&out[(size_t)row * DD + c] = r;
    }
}

// ---------------------------------------------------------------------------
extern "C" void kernel_launch(void* const* d_in, const int* in_sizes, int n_in,
                              void* d_out, int out_size)
{
    (void)in_sizes; (void)n_in; (void)out_size;
    const float* inp   = (const float*)d_in[0];
    const int*   mask  = (const int*)d_in[1];
    const float* Wqkv  = (const float*)d_in[2];
    const float* bqkv  = (const float*)d_in[3];
    const float* Wo    = (const float*)d_in[4];
    const float* gamma = (const float*)d_in[5];
    const float* beta  = (const float*)d_in[6];
    float* out = (float*)d_out;

    bf16 *inpb, *wqkvb, *wob, *qb, *kc, *vc, *attnb;
    float* y;
    int *idx, *cnt;
    cudaGetSymbolAddress((void**)&inpb,  g_inpb);
    cudaGetSymbolAddress((void**)&wqkvb, g_wqkvb);
    cudaGetSymbolAddress((void**)&wob,   g_wob);
    cudaGetSymbolAddress((void**)&qb,    g_qb);
    cudaGetSymbolAddress((void**)&kc,    g_kc);
    cudaGetSymbolAddress((void**)&vc,    g_vc);
    cudaGetSymbolAddress((void**)&attnb, g_attnb);
    cudaGetSymbolAddress((void**)&y,     g_y);
    cudaGetSymbolAddress((void**)&idx,   g_idx);
    cudaGetSymbolAddress((void**)&cnt,   g_cnt);

    cudaFuncSetAttribute(qkv_gemm,
                         cudaFuncAttributeMaxDynamicSharedMemorySize, GSMEM_BYTES);
    cudaFuncSetAttribute(hgemm_proj,
                         cudaFuncAttributeMaxDynamicSharedMemorySize, GSMEM_BYTES);
    cudaFuncSetAttribute(flash_bf16,
                         cudaFuncAttributeMaxDynamicSharedMemorySize, FSMEM_BYTES);

    // PDL launch attribute (dependent may start during predecessor's epilogue)
    cudaLaunchAttribute pdl[1];
    pdl[0].id = cudaLaunchAttributeProgrammaticStreamSerialization;
    pdl[0].val.programmaticStreamSerializationAllowed = 1;

    // 0) fused conversions + key compaction
    preproc<<<PRE_TOTAL, 256>>>(inp, Wqkv, Wo, mask, inpb, wqkvb, wob, idx, cnt);

    // 1) unified Q + gathered-KV GEMM
    {
        cudaLaunchConfig_t cfg = {};
        cfg.gridDim = dim3(768, 1, 1); cfg.blockDim = dim3(256, 1, 1);
        cfg.dynamicSmemBytes = GSMEM_BYTES; cfg.stream = 0;
        cfg.attrs = pdl; cfg.numAttrs = 1;
        cudaLaunchKernelEx(&cfg, qkv_gemm, inpb, wqkvb, bqkv,
                           (const int*)idx, (const int*)cnt, qb, kc, vc);
    }

    // 2) attention over ~cnt keys
    {
        cudaLaunchConfig_t cfg = {};
        cfg.gridDim = dim3(BB * HH, SS / 128, 1); cfg.blockDim = dim3(256, 1, 1);
        cfg.dynamicSmemBytes = FSMEM_BYTES; cfg.stream = 0;
        cfg.attrs = pdl; cfg.numAttrs = 1;
        cudaLaunchKernelEx(&cfg, flash_bf16, (const bf16*)qb, (const bf16*)kc,
                           (const bf16*)vc, (const int*)cnt, attnb);
    }

    // 3) y = inp + attn @ Wo^T  (128x256 tile, occupancy-1: measured best)
    {
        cudaLaunchConfig_t cfg = {};
        cfg.gridDim = dim3(DD / 256, MTOK / 128, 1); cfg.blockDim = dim3(256, 1, 1);
        cfg.dynamicSmemBytes = GSMEM_BYTES; cfg.stream = 0;
        cfg.attrs = pdl; cfg.numAttrs = 1;
        cudaLaunchKernelEx(&cfg, hgemm_proj, (const bf16*)attnb, (const bf16*)wob,
                           inp, y, MTOK, DD, DD);
    }

    // 4) out = LayerNorm(y)
    {
        cudaLaunchConfig_t cfg = {};
        cfg.gridDim = dim3(MTOK / 8, 1, 1); cfg.blockDim = dim3(256, 1, 1);
        cfg.dynamicSmemBytes = 0; cfg.stream = 0;
        cfg.attrs = pdl; cfg.numAttrs = 1;
        cudaLaunchKernelEx(&cfg, ln_kernel, (const float*)y, gamma, beta, out);
    }
}